// round 1
// baseline (speedup 1.0000x reference)
#include <cuda_runtime.h>
#include <math_constants.h>
#include <cstddef>

#define N_USERS 10000
#define N_NEWS  10000
#define N_ENT   100000
#define DIM     64
#define KNB     20
#define NNZ_CNT 500000

#define NQT 157      // ceil(10000/64) query tiles
#define NKT 157      // key tiles
#define KSPLIT 8
#define NUNITS (NQT*KSPLIT)

// partial per unit: 64 rows x (64 O-cols + m + l) = 64*66 floats
__device__ float g_part[(size_t)NUNITS * 64 * 66];

// ---------------------------------------------------------------------------
// Aggregation kernel: one warp per row, lane owns d = {2*lane, 2*lane+1}.
// hnorm[d] = |head[d]| * sqrt(sum_k rel[k,d]^2)
// att[k]   = sum_d tail[k,d]*rel[k,d]*hnorm[d];  w = softmax(att^2)
// out[d]   = sum_k w[k]*tail[k,d]   (online softmax, single tail gather)
// ---------------------------------------------------------------------------
__global__ void __launch_bounds__(256) agg_kernel(
    const float* __restrict__ head,
    const float* __restrict__ ent,
    const float* __restrict__ rel,
    const int*   __restrict__ nbe,
    const int*   __restrict__ nbr,
    float* __restrict__ out, int N)
{
    int w    = (blockIdx.x * blockDim.x + threadIdx.x) >> 5;
    int lane = threadIdx.x & 31;
    if (w >= N) return;

    const float2 h = ((const float2*)(head + (size_t)w * DIM))[lane];
    const int base = w * KNB;

    float sx = 0.f, sy = 0.f;
    #pragma unroll
    for (int k = 0; k < KNB; k++) {
        int ri = __ldg(nbr + base + k);
        float2 rr = ((const float2*)(rel + (size_t)ri * DIM))[lane];
        sx += rr.x * rr.x;
        sy += rr.y * rr.y;
    }
    float hnx = fabsf(h.x) * sqrtf(sx);
    float hny = fabsf(h.y) * sqrtf(sy);

    float m = 0.f, l = 0.f, ax = 0.f, ay = 0.f;
    #pragma unroll
    for (int k = 0; k < KNB; k++) {
        int ri = __ldg(nbr + base + k);
        int ei = __ldg(nbe + base + k);
        float2 rr = ((const float2*)(rel + (size_t)ri * DIM))[lane];
        float2 tt = ((const float2*)(ent + (size_t)ei * DIM))[lane];
        float p = tt.x * rr.x * hnx + tt.y * rr.y * hny;
        #pragma unroll
        for (int off = 16; off; off >>= 1)
            p += __shfl_xor_sync(0xffffffffu, p, off);
        float a2 = p * p;
        if (k == 0) {
            m = a2; l = 1.f; ax = tt.x; ay = tt.y;
        } else {
            float mn = fmaxf(m, a2);
            float sc = __expf(m - mn);
            float e  = __expf(a2 - mn);
            l  = l  * sc + e;
            ax = ax * sc + e * tt.x;
            ay = ay * sc + e * tt.y;
            m = mn;
        }
    }
    float inv = 1.f / l;
    ((float2*)(out + (size_t)w * DIM))[lane] = make_float2(ax * inv, ay * inv);
}

// ---------------------------------------------------------------------------
// Segment sum: one warp per nnz; lane handles 2 d's. Atomic adds into
// zero-initialized user region (L2-resident, 2.5 MB).
// ---------------------------------------------------------------------------
__global__ void __launch_bounds__(256) segsum_kernel(
    const int*   __restrict__ rows,
    const int*   __restrict__ cols,
    const float* __restrict__ vals,
    const float* __restrict__ news_agg,
    float* __restrict__ user_seg, int nnz)
{
    int w    = (blockIdx.x * blockDim.x + threadIdx.x) >> 5;
    int lane = threadIdx.x & 31;
    if (w >= nnz) return;
    int r   = __ldg(rows + w);
    int c   = __ldg(cols + w);
    float v = __ldg(vals + w);
    float2 g = ((const float2*)(news_agg + (size_t)c * DIM))[lane];
    atomicAdd(user_seg + (size_t)r * DIM + 2 * lane,     v * g.x);
    atomicAdd(user_seg + (size_t)r * DIM + 2 * lane + 1, v * g.y);
}

// ---------------------------------------------------------------------------
// Flash-attention style: Q = user_emb, K = V = news_agg.
// Block = one (qtile, keysplit) unit: TM=64 queries, key tiles 64 strided by
// KSPLIT. 256 threads = 16(ty) x 16(tx); thread tile: rows {4ty+i},
// S-cols/d-cols {16j+tx} (strided to avoid smem bank conflicts).
// Writes unnormalized partial (O, m, l) to g_part.
// ---------------------------------------------------------------------------
#define SMEM_FLOATS (64*65 + 64*65 + 64*64 + 64*65)
#define SMEM_BYTES  (SMEM_FLOATS * 4)

__global__ void __launch_bounds__(256) attn_kernel(
    const float* __restrict__ Q,
    const float* __restrict__ KV)
{
    extern __shared__ float smem[];
    float* QS = smem;               // [64][65]
    float* KS = QS + 64 * 65;       // [64][65]
    float* VS = KS + 64 * 65;       // [64][64]
    float* PS = VS + 64 * 64;       // [64][65]

    const int unit = blockIdx.x;
    const int qt = unit / KSPLIT;
    const int ks = unit % KSPLIT;
    const int tid = threadIdx.x;
    const int ty = tid >> 4;
    const int tx = tid & 15;

    // load Q tile (zero-pad OOB rows)
    for (int idx = tid; idx < 64 * 64; idx += 256) {
        int r = idx >> 6, c = idx & 63;
        int gr = qt * 64 + r;
        QS[r * 65 + c] = (gr < N_USERS) ? Q[(size_t)gr * DIM + c] : 0.f;
    }

    float o[4][4];
    float m[4], l[4];
    #pragma unroll
    for (int i = 0; i < 4; i++) {
        m[i] = -CUDART_INF_F; l[i] = 0.f;
        #pragma unroll
        for (int j = 0; j < 4; j++) o[i][j] = 0.f;
    }
    __syncthreads();

    for (int kt = ks; kt < NKT; kt += KSPLIT) {
        // load K/V tile: KS padded (S-gemm reads), VS natural (O-gemm reads)
        for (int idx = tid; idx < 64 * 16; idx += 256) {
            int r = idx >> 4, q4 = idx & 15;
            int gr = kt * 64 + r;
            float4 v = make_float4(0.f, 0.f, 0.f, 0.f);
            if (gr < N_NEWS) v = ((const float4*)(KV + (size_t)gr * DIM))[q4];
            int c = q4 * 4;
            KS[r * 65 + c + 0] = v.x;
            KS[r * 65 + c + 1] = v.y;
            KS[r * 65 + c + 2] = v.z;
            KS[r * 65 + c + 3] = v.w;
            ((float4*)(VS + r * 64))[q4] = v;
        }
        __syncthreads();

        // S = Qtile @ Ktile^T
        float s[4][4];
        #pragma unroll
        for (int i = 0; i < 4; i++)
            #pragma unroll
            for (int j = 0; j < 4; j++) s[i][j] = 0.f;

        #pragma unroll 4
        for (int kk = 0; kk < 64; kk++) {
            float qv[4], kv[4];
            #pragma unroll
            for (int i = 0; i < 4; i++) qv[i] = QS[(4 * ty + i) * 65 + kk];
            #pragma unroll
            for (int j = 0; j < 4; j++) kv[j] = KS[(16 * j + tx) * 65 + kk];
            #pragma unroll
            for (int i = 0; i < 4; i++)
                #pragma unroll
                for (int j = 0; j < 4; j++)
                    s[i][j] = fmaf(qv[i], kv[j], s[i][j]);
        }

        // mask invalid keys on the last tile
        if (kt == NKT - 1) {
            #pragma unroll
            for (int j = 0; j < 4; j++) {
                int gc = kt * 64 + 16 * j + tx;
                if (gc >= N_NEWS) {
                    #pragma unroll
                    for (int i = 0; i < 4; i++) s[i][j] = -CUDART_INF_F;
                }
            }
        }

        // online softmax update per row (reduce over tx: 16 lanes)
        #pragma unroll
        for (int i = 0; i < 4; i++) {
            float mt = fmaxf(fmaxf(s[i][0], s[i][1]), fmaxf(s[i][2], s[i][3]));
            #pragma unroll
            for (int off = 8; off; off >>= 1)
                mt = fmaxf(mt, __shfl_xor_sync(0xffffffffu, mt, off));
            float mn = fmaxf(m[i], mt);
            float sc = __expf(m[i] - mn);   // 0 when m == -inf
            float rs = 0.f;
            #pragma unroll
            for (int j = 0; j < 4; j++) {
                s[i][j] = __expf(s[i][j] - mn);
                rs += s[i][j];
            }
            #pragma unroll
            for (int off = 8; off; off >>= 1)
                rs += __shfl_xor_sync(0xffffffffu, rs, off);
            l[i] = l[i] * sc + rs;
            #pragma unroll
            for (int j = 0; j < 4; j++) o[i][j] *= sc;
            m[i] = mn;
        }

        __syncthreads();
        #pragma unroll
        for (int i = 0; i < 4; i++)
            #pragma unroll
            for (int j = 0; j < 4; j++)
                PS[(4 * ty + i) * 65 + 16 * j + tx] = s[i][j];
        __syncthreads();

        // O += P @ Vtile
        #pragma unroll 4
        for (int jk = 0; jk < 64; jk++) {
            float pv[4], vv[4];
            #pragma unroll
            for (int i = 0; i < 4; i++) pv[i] = PS[(4 * ty + i) * 65 + jk];
            #pragma unroll
            for (int j = 0; j < 4; j++) vv[j] = VS[jk * 64 + 16 * j + tx];
            #pragma unroll
            for (int i = 0; i < 4; i++)
                #pragma unroll
                for (int j = 0; j < 4; j++)
                    o[i][j] = fmaf(pv[i], vv[j], o[i][j]);
        }
        __syncthreads();
    }

    // write partial (unnormalized O acc, m, l)
    float* pb = g_part + (size_t)unit * (64 * 66);
    #pragma unroll
    for (int i = 0; i < 4; i++) {
        int r = 4 * ty + i;
        #pragma unroll
        for (int j = 0; j < 4; j++)
            pb[r * 66 + 16 * j + tx] = o[i][j];
        if (tx == 0) {
            pb[r * 66 + 64] = m[i];
            pb[r * 66 + 65] = l[i];
        }
    }
}

// ---------------------------------------------------------------------------
// Combine KSPLIT partials per user row + final epilogue:
//   attn = (sum_s e_s * O_s) / (sum_s e_s * l_s),  e_s = exp(m_s - max m)
//   user_out = seg + attn * seg       (seg read in-place from user_out)
// One warp per row, lane owns 2 d's.
// ---------------------------------------------------------------------------
__global__ void __launch_bounds__(256) combine_kernel(float* __restrict__ user_out)
{
    int w    = (blockIdx.x * blockDim.x + threadIdx.x) >> 5;
    int lane = threadIdx.x & 31;
    if (w >= N_USERS) return;
    int qt = w >> 6, r = w & 63;
    const float* base = g_part + (size_t)qt * KSPLIT * (64 * 66) + r * 66;

    float M = -CUDART_INF_F;
    float ms[KSPLIT], ls[KSPLIT];
    #pragma unroll
    for (int s = 0; s < KSPLIT; s++) {
        ms[s] = base[(size_t)s * (64 * 66) + 64];
        ls[s] = base[(size_t)s * (64 * 66) + 65];
        M = fmaxf(M, ms[s]);
    }
    float L = 0.f, ax = 0.f, ay = 0.f;
    #pragma unroll
    for (int s = 0; s < KSPLIT; s++) {
        float e = __expf(ms[s] - M);
        L += e * ls[s];
        float2 ov = ((const float2*)(base + (size_t)s * (64 * 66)))[lane];
        ax += e * ov.x;
        ay += e * ov.y;
    }
    float inv = 1.f / L;
    float2* up = (float2*)(user_out + (size_t)w * DIM);
    float2 sg = up[lane];
    up[lane] = make_float2(sg.x + ax * inv * sg.x,
                           sg.y + ay * inv * sg.y);
}

// ---------------------------------------------------------------------------
extern "C" void kernel_launch(void* const* d_in, const int* in_sizes, int n_in,
                              void* d_out, int out_size)
{
    const float* user_emb = (const float*)d_in[0];
    const float* news_emb = (const float*)d_in[1];
    const float* ent_emb  = (const float*)d_in[2];
    const float* rel_emb  = (const float*)d_in[3];
    const int*   news_ent = (const int*)d_in[4];
    const int*   news_rel = (const int*)d_in[5];
    const int*   nb_ent   = (const int*)d_in[6];
    const int*   nb_rel   = (const int*)d_in[7];
    const int*   irows    = (const int*)d_in[8];
    const int*   icols    = (const int*)d_in[9];
    const float* ivals    = (const float*)d_in[10];

    float* out      = (float*)d_out;
    float* news_out = out;
    float* ent_out  = out + (size_t)N_NEWS * DIM;
    float* user_out = ent_out + (size_t)N_ENT * DIM;

    // news aggregation (head = news embeddings)
    agg_kernel<<<(N_NEWS + 7) / 8, 256>>>(news_emb, ent_emb, rel_emb,
                                          news_ent, news_rel, news_out, N_NEWS);
    // entity aggregation (head = entity embeddings, identity gather)
    agg_kernel<<<(N_ENT + 7) / 8, 256>>>(ent_emb, ent_emb, rel_emb,
                                         nb_ent, nb_rel, ent_out, N_ENT);
    // sparse segment sum into user region
    cudaMemsetAsync(user_out, 0, (size_t)N_USERS * DIM * sizeof(float));
    segsum_kernel<<<(NNZ_CNT + 7) / 8, 256>>>(irows, icols, ivals,
                                              news_out, user_out, NNZ_CNT);
    // attention: softmax(user_emb @ news_agg^T) @ news_agg (split-K partials)
    cudaFuncSetAttribute(attn_kernel,
                         cudaFuncAttributeMaxDynamicSharedMemorySize, SMEM_BYTES);
    attn_kernel<<<NUNITS, 256, SMEM_BYTES>>>(user_emb, news_out);
    // combine partials + epilogue: user_out = seg * (1 + attn)
    combine_kernel<<<(N_USERS + 7) / 8, 256>>>(user_out);
}

// round 4
// speedup vs baseline: 2.3564x; 2.3564x over previous
#include <cuda_runtime.h>
#include <cuda_fp16.h>
#include <math_constants.h>
#include <cstdint>
#include <cstddef>

#define N_USERS 10000
#define N_NEWS  10000
#define N_ENT   100000
#define DIM     64
#define KNB     20
#define NNZ_CNT 500000

// -------------------- attention (mma.sync fp16) config ---------------------
#define QTILE   128
#define KTILE   64
#define QTILES  79                  // ceil(10000/128)
#define NKT     157                 // ceil(10000/64)
#define KSPL    8
#define ATT_UNITS (QTILES * KSPL)   // 632

__device__ float g_po[(size_t)ATT_UNITS * 128 * 64];
__device__ float g_pl[(size_t)ATT_UNITS * 128];
__device__ float g_pm[(size_t)ATT_UNITS * 128];

// smem map (bytes, within dynamic smem): fp16 tiles, 128B/row, 16B-chunk swizzle
#define SQHI 0
#define SQLO 16384
#define SKHI 32768
#define SKLO 40960
#define SMEM_ATT 49152

// ----------------------------- helpers -------------------------------------
__device__ __forceinline__ uint32_t smem_u32(const void* p) {
    uint32_t a;
    asm("{ .reg .u64 t; cvta.to.shared.u64 t, %1; cvt.u32.u64 %0, t; }"
        : "=r"(a) : "l"(p));
    return a;
}
__device__ __forceinline__ void ldsm4(uint32_t r[4], uint32_t addr) {
    asm volatile("ldmatrix.sync.aligned.m8n8.x4.shared.b16 {%0,%1,%2,%3}, [%4];"
        : "=r"(r[0]), "=r"(r[1]), "=r"(r[2]), "=r"(r[3]) : "r"(addr));
}
__device__ __forceinline__ void ldsm4t(uint32_t r[4], uint32_t addr) {
    asm volatile("ldmatrix.sync.aligned.m8n8.x4.trans.shared.b16 {%0,%1,%2,%3}, [%4];"
        : "=r"(r[0]), "=r"(r[1]), "=r"(r[2]), "=r"(r[3]) : "r"(addr));
}
__device__ __forceinline__ void mma16816(float d[4], const uint32_t a[4],
                                         uint32_t b0, uint32_t b1) {
    asm volatile(
        "mma.sync.aligned.m16n8k16.row.col.f32.f16.f16.f32 "
        "{%0,%1,%2,%3}, {%4,%5,%6,%7}, {%8,%9}, {%0,%1,%2,%3};"
        : "+f"(d[0]), "+f"(d[1]), "+f"(d[2]), "+f"(d[3])
        : "r"(a[0]), "r"(a[1]), "r"(a[2]), "r"(a[3]), "r"(b0), "r"(b1));
}
__device__ __forceinline__ uint32_t f2h2(float x, float y) {
    __half2 h = __floats2half2_rn(x, y);
    return *reinterpret_cast<uint32_t*>(&h);
}
__device__ __forceinline__ float2 h22f2(uint32_t u) {
    __half2 h = *reinterpret_cast<__half2*>(&u);
    return __half22float2(h);
}
// split a float4 pair covering 8 consecutive halves into hi/lo 16B chunks
__device__ __forceinline__ void split_chunk(float4 a, float4 b,
                                            uint4& hi, uint4& lo) {
    hi = make_uint4(f2h2(a.x, a.y), f2h2(a.z, a.w), f2h2(b.x, b.y), f2h2(b.z, b.w));
    float2 r0 = h22f2(hi.x), r1 = h22f2(hi.y), r2 = h22f2(hi.z), r3 = h22f2(hi.w);
    lo = make_uint4(f2h2(a.x - r0.x, a.y - r0.y), f2h2(a.z - r1.x, a.w - r1.y),
                    f2h2(b.x - r2.x, b.y - r2.y), f2h2(b.z - r3.x, b.w - r3.y));
}
__device__ __forceinline__ uint32_t swadr(uint32_t base, uint32_t row, uint32_t chunk) {
    return base + row * 128u + ((chunk ^ (row & 7u)) << 4);
}

// ---------------------------------------------------------------------------
// FA2 on mma.sync fp16: CTA = 128 q-rows x key tiles {ks, ks+KSPL, ...}.
// S = Qhi*Khi + Qlo*Khi + Qhi*Klo (fp32-quality); O = P*(Vhi+Vlo), V==K tiles.
// Writes unnormalized partial (O, m, l) per split.
// ---------------------------------------------------------------------------
__global__ void __launch_bounds__(128, 2)
attn_mma_kernel(const float* __restrict__ Q, const float* __restrict__ KV)
{
    extern __shared__ char smraw[];
    const uint32_t sb = smem_u32(smraw);
    const int tid  = threadIdx.x;
    const int wrp  = tid >> 5;
    const int lane = tid & 31;
    const int qt   = blockIdx.x / KSPL;
    const int ks   = blockIdx.x % KSPL;
    const int nt   = (NKT - ks + KSPL - 1) / KSPL;

    // ---- stage Q tile (thread = one row), hi/lo fp16, swizzled ----
    {
        int gr = qt * QTILE + tid;
        const float4* row = (const float4*)(Q + (size_t)gr * DIM);
        #pragma unroll
        for (int i = 0; i < 8; i++) {
            float4 a, b;
            if (gr < N_USERS) { a = row[2 * i]; b = row[2 * i + 1]; }
            else { a = make_float4(0.f,0.f,0.f,0.f); b = a; }
            uint4 hi, lo;
            split_chunk(a, b, hi, lo);
            *(uint4*)((uintptr_t)smraw + SQHI + (swadr(0, tid, i))) = hi;
            *(uint4*)((uintptr_t)smraw + SQLO + (swadr(0, tid, i))) = lo;
        }
    }
    __syncthreads();

    // ---- load Q fragments to registers: qh/ql[mt][kstep][4] ----
    uint32_t qh[2][4][4], ql[2][4][4];
    #pragma unroll
    for (int mt = 0; mt < 2; mt++) {
        #pragma unroll
        for (int kp = 0; kp < 4; kp++) {
            uint32_t row = 32 * wrp + 16 * mt + ((lane >> 3) & 1) * 8 + (lane & 7);
            uint32_t ch  = 2 * kp + ((lane >> 4) & 1);
            ldsm4(qh[mt][kp], swadr(sb + SQHI, row, ch));
            ldsm4(ql[mt][kp], swadr(sb + SQLO, row, ch));
        }
    }

    float o[2][8][4];
    float m[4], l[4];
    #pragma unroll
    for (int mt = 0; mt < 2; mt++)
        #pragma unroll
        for (int n = 0; n < 8; n++)
            #pragma unroll
            for (int k = 0; k < 4; k++) o[mt][n][k] = 0.f;
    #pragma unroll
    for (int i = 0; i < 4; i++) { m[i] = -CUDART_INF_F; l[i] = 0.f; }

    for (int t = 0; t < nt; t++) {
        const int kbase = (ks + KSPL * t) * KTILE;
        __syncthreads();   // prior O-phase ldmatrix done before overwrite

        // ---- load + split K/V tile (2 threads per key row) ----
        {
            int r  = tid >> 1;
            int hc = tid & 1;
            const float4* src = (const float4*)(KV + ((size_t)(kbase + r)) * DIM) + hc * 8;
            #pragma unroll
            for (int i = 0; i < 4; i++) {
                float4 a = src[2 * i], b = src[2 * i + 1];
                uint4 hi, lo;
                split_chunk(a, b, hi, lo);
                uint32_t c = (uint32_t)(hc * 4 + i);
                *(uint4*)((uintptr_t)smraw + SKHI + swadr(0, r, c)) = hi;
                *(uint4*)((uintptr_t)smraw + SKLO + swadr(0, r, c)) = lo;
            }
        }
        __syncthreads();

        // ---- S = Q @ K^T (3-term split) ----
        float s[2][8][4];
        #pragma unroll
        for (int mt = 0; mt < 2; mt++)
            #pragma unroll
            for (int n = 0; n < 8; n++)
                #pragma unroll
                for (int k = 0; k < 4; k++) s[mt][n][k] = 0.f;

        #pragma unroll
        for (int kp = 0; kp < 4; kp++) {
            #pragma unroll
            for (int p = 0; p < 4; p++) {
                uint32_t key = 16u * p + ((lane >> 4) & 1) * 8 + (lane & 7);
                uint32_t ch  = 2u * kp + ((lane >> 3) & 1);
                uint32_t bh[4], bl[4];
                ldsm4(bh, swadr(sb + SKHI, key, ch));
                ldsm4(bl, swadr(sb + SKLO, key, ch));
                #pragma unroll
                for (int mt = 0; mt < 2; mt++) {
                    mma16816(s[mt][2*p],   qh[mt][kp], bh[0], bh[1]);
                    mma16816(s[mt][2*p],   ql[mt][kp], bh[0], bh[1]);
                    mma16816(s[mt][2*p],   qh[mt][kp], bl[0], bl[1]);
                    mma16816(s[mt][2*p+1], qh[mt][kp], bh[2], bh[3]);
                    mma16816(s[mt][2*p+1], ql[mt][kp], bh[2], bh[3]);
                    mma16816(s[mt][2*p+1], qh[mt][kp], bl[2], bl[3]);
                }
            }
        }

        // ---- mask tail keys ----
        if (kbase + KTILE > N_NEWS) {
            #pragma unroll
            for (int n = 0; n < 8; n++) {
                int c0 = kbase + 8 * n + (lane & 3) * 2;
                #pragma unroll
                for (int d = 0; d < 2; d++) {
                    if (c0 + d >= N_NEWS) {
                        #pragma unroll
                        for (int mt = 0; mt < 2; mt++) {
                            s[mt][n][d]     = -CUDART_INF_F;
                            s[mt][n][d + 2] = -CUDART_INF_F;
                        }
                    }
                }
            }
        }

        // ---- online softmax ----
        #pragma unroll
        for (int mt = 0; mt < 2; mt++) {
            #pragma unroll
            for (int h = 0; h < 2; h++) {
                const int i = mt * 2 + h;
                float mx = -CUDART_INF_F;
                #pragma unroll
                for (int n = 0; n < 8; n++)
                    mx = fmaxf(mx, fmaxf(s[mt][n][2*h], s[mt][n][2*h+1]));
                mx = fmaxf(mx, __shfl_xor_sync(0xffffffffu, mx, 1));
                mx = fmaxf(mx, __shfl_xor_sync(0xffffffffu, mx, 2));
                float mn = fmaxf(m[i], mx);
                float sc = __expf(m[i] - mn);
                m[i] = mn;
                l[i] *= sc;
                #pragma unroll
                for (int n = 0; n < 8; n++) {
                    o[mt][n][2*h]   *= sc;
                    o[mt][n][2*h+1] *= sc;
                    float e0 = __expf(s[mt][n][2*h]   - mn);
                    float e1 = __expf(s[mt][n][2*h+1] - mn);
                    // round to fp16 and keep l consistent with the MMA's P
                    uint32_t u = f2h2(e0, e1);
                    float2 er = h22f2(u);
                    s[mt][n][2*h]   = er.x;
                    s[mt][n][2*h+1] = er.y;
                    l[i] += er.x + er.y;
                }
            }
        }

        // ---- O += P @ V (V == K tiles, via trans ldmatrix; hi+lo) ----
        #pragma unroll
        for (int kk = 0; kk < 4; kk++) {
            uint32_t pa[2][4];
            #pragma unroll
            for (int mt = 0; mt < 2; mt++) {
                pa[mt][0] = f2h2(s[mt][2*kk][0],   s[mt][2*kk][1]);
                pa[mt][1] = f2h2(s[mt][2*kk][2],   s[mt][2*kk][3]);
                pa[mt][2] = f2h2(s[mt][2*kk+1][0], s[mt][2*kk+1][1]);
                pa[mt][3] = f2h2(s[mt][2*kk+1][2], s[mt][2*kk+1][3]);
            }
            #pragma unroll
            for (int p = 0; p < 4; p++) {
                uint32_t key = 16u * kk + ((lane >> 3) & 1) * 8 + (lane & 7);
                uint32_t ch  = 2u * p + ((lane >> 4) & 1);
                uint32_t vh[4], vl[4];
                ldsm4t(vh, swadr(sb + SKHI, key, ch));
                ldsm4t(vl, swadr(sb + SKLO, key, ch));
                #pragma unroll
                for (int mt = 0; mt < 2; mt++) {
                    mma16816(o[mt][2*p],   pa[mt], vh[0], vh[1]);
                    mma16816(o[mt][2*p],   pa[mt], vl[0], vl[1]);
                    mma16816(o[mt][2*p+1], pa[mt], vh[2], vh[3]);
                    mma16816(o[mt][2*p+1], pa[mt], vl[2], vl[3]);
                }
            }
        }
    }

    // ---- reduce l across the 4 lanes of each row group (m already shared;
    //      per-tile scale factors were identical across lanes, so a single
    //      final reduction is exact). THIS was the R3 bug. ----
    #pragma unroll
    for (int i = 0; i < 4; i++) {
        l[i] += __shfl_xor_sync(0xffffffffu, l[i], 1);
        l[i] += __shfl_xor_sync(0xffffffffu, l[i], 2);
    }

    // ---- write partial (unnormalized O, m, l) ----
    const int g = lane >> 2;
    #pragma unroll
    for (int mt = 0; mt < 2; mt++) {
        #pragma unroll
        for (int h = 0; h < 2; h++) {
            int row = 32 * wrp + 16 * mt + 8 * h + g;
            float* pb = g_po + ((size_t)blockIdx.x * 128 + row) * 64;
            #pragma unroll
            for (int n = 0; n < 8; n++) {
                int c = 8 * n + (lane & 3) * 2;
                *(float2*)(pb + c) = make_float2(o[mt][n][2*h], o[mt][n][2*h+1]);
            }
            if ((lane & 3) == 0) {
                g_pm[(size_t)blockIdx.x * 128 + row] = m[mt * 2 + h];
                g_pl[(size_t)blockIdx.x * 128 + row] = l[mt * 2 + h];
            }
        }
    }
}

// ---------------------------------------------------------------------------
// Aggregation kernel (as R1): one warp per row.
// ---------------------------------------------------------------------------
__global__ void __launch_bounds__(256) agg_kernel(
    const float* __restrict__ head,
    const float* __restrict__ ent,
    const float* __restrict__ rel,
    const int*   __restrict__ nbe,
    const int*   __restrict__ nbr,
    float* __restrict__ out, int N)
{
    int w    = (blockIdx.x * blockDim.x + threadIdx.x) >> 5;
    int lane = threadIdx.x & 31;
    if (w >= N) return;

    const float2 h = ((const float2*)(head + (size_t)w * DIM))[lane];
    const int base = w * KNB;

    float sx = 0.f, sy = 0.f;
    #pragma unroll
    for (int k = 0; k < KNB; k++) {
        int ri = __ldg(nbr + base + k);
        float2 rr = ((const float2*)(rel + (size_t)ri * DIM))[lane];
        sx += rr.x * rr.x;
        sy += rr.y * rr.y;
    }
    float hnx = fabsf(h.x) * sqrtf(sx);
    float hny = fabsf(h.y) * sqrtf(sy);

    float m = 0.f, l = 0.f, ax = 0.f, ay = 0.f;
    #pragma unroll
    for (int k = 0; k < KNB; k++) {
        int ri = __ldg(nbr + base + k);
        int ei = __ldg(nbe + base + k);
        float2 rr = ((const float2*)(rel + (size_t)ri * DIM))[lane];
        float2 tt = ((const float2*)(ent + (size_t)ei * DIM))[lane];
        float p = tt.x * rr.x * hnx + tt.y * rr.y * hny;
        #pragma unroll
        for (int off = 16; off; off >>= 1)
            p += __shfl_xor_sync(0xffffffffu, p, off);
        float a2 = p * p;
        if (k == 0) {
            m = a2; l = 1.f; ax = tt.x; ay = tt.y;
        } else {
            float mn = fmaxf(m, a2);
            float sc = __expf(m - mn);
            float e  = __expf(a2 - mn);
            l  = l  * sc + e;
            ax = ax * sc + e * tt.x;
            ay = ay * sc + e * tt.y;
            m = mn;
        }
    }
    float inv = 1.f / l;
    ((float2*)(out + (size_t)w * DIM))[lane] = make_float2(ax * inv, ay * inv);
}

// ---------------------------------------------------------------------------
__global__ void __launch_bounds__(256) segsum_kernel(
    const int*   __restrict__ rows,
    const int*   __restrict__ cols,
    const float* __restrict__ vals,
    const float* __restrict__ news_agg,
    float* __restrict__ user_seg, int nnz)
{
    int w    = (blockIdx.x * blockDim.x + threadIdx.x) >> 5;
    int lane = threadIdx.x & 31;
    if (w >= nnz) return;
    int r   = __ldg(rows + w);
    int c   = __ldg(cols + w);
    float v = __ldg(vals + w);
    float2 g = ((const float2*)(news_agg + (size_t)c * DIM))[lane];
    atomicAdd(user_seg + (size_t)r * DIM + 2 * lane,     v * g.x);
    atomicAdd(user_seg + (size_t)r * DIM + 2 * lane + 1, v * g.y);
}

// ---------------------------------------------------------------------------
// Combine split partials with per-split (m, l):
//   M = max m_s; attn = (sum e_s O_s) / (sum e_s l_s);  user = seg*(1+attn)
// ---------------------------------------------------------------------------
__global__ void __launch_bounds__(256) combine_kernel(float* __restrict__ user_out)
{
    int w    = (blockIdx.x * blockDim.x + threadIdx.x) >> 5;
    int lane = threadIdx.x & 31;
    if (w >= N_USERS) return;
    int qt = w >> 7, r = w & 127;

    float M = -CUDART_INF_F;
    float ms[KSPL], ls[KSPL];
    #pragma unroll
    for (int s = 0; s < KSPL; s++) {
        size_t u = (size_t)(qt * KSPL + s);
        ms[s] = g_pm[u * 128 + r];
        ls[s] = g_pl[u * 128 + r];
        M = fmaxf(M, ms[s]);
    }
    float L = 0.f, ax = 0.f, ay = 0.f;
    #pragma unroll
    for (int s = 0; s < KSPL; s++) {
        size_t u = (size_t)(qt * KSPL + s);
        float e = __expf(ms[s] - M);
        L += e * ls[s];
        float2 o2 = ((const float2*)(g_po + (u * 128 + r) * 64))[lane];
        ax += e * o2.x;
        ay += e * o2.y;
    }
    float inv = 1.f / L;
    float2* up = (float2*)(user_out + (size_t)w * DIM);
    float2 sg = up[lane];
    up[lane] = make_float2(sg.x + ax * inv * sg.x,
                           sg.y + ay * inv * sg.y);
}

// ---------------------------------------------------------------------------
extern "C" void kernel_launch(void* const* d_in, const int* in_sizes, int n_in,
                              void* d_out, int out_size)
{
    const float* user_emb = (const float*)d_in[0];
    const float* news_emb = (const float*)d_in[1];
    const float* ent_emb  = (const float*)d_in[2];
    const float* rel_emb  = (const float*)d_in[3];
    const int*   news_ent = (const int*)d_in[4];
    const int*   news_rel = (const int*)d_in[5];
    const int*   nb_ent   = (const int*)d_in[6];
    const int*   nb_rel   = (const int*)d_in[7];
    const int*   irows    = (const int*)d_in[8];
    const int*   icols    = (const int*)d_in[9];
    const float* ivals    = (const float*)d_in[10];

    float* out      = (float*)d_out;
    float* news_out = out;
    float* ent_out  = out + (size_t)N_NEWS * DIM;
    float* user_out = ent_out + (size_t)N_ENT * DIM;

    agg_kernel<<<(N_NEWS + 7) / 8, 256>>>(news_emb, ent_emb, rel_emb,
                                          news_ent, news_rel, news_out, N_NEWS);
    agg_kernel<<<(N_ENT + 7) / 8, 256>>>(ent_emb, ent_emb, rel_emb,
                                         nb_ent, nb_rel, ent_out, N_ENT);
    cudaMemsetAsync(user_out, 0, (size_t)N_USERS * DIM * sizeof(float));
    segsum_kernel<<<(NNZ_CNT + 7) / 8, 256>>>(irows, icols, ivals,
                                              news_out, user_out, NNZ_CNT);
    cudaFuncSetAttribute(attn_mma_kernel,
                         cudaFuncAttributeMaxDynamicSharedMemorySize, SMEM_ATT);
    attn_mma_kernel<<<ATT_UNITS, 128, SMEM_ATT>>>(user_emb, news_out);
    combine_kernel<<<(N_USERS + 7) / 8, 256>>>(user_out);
}

// round 5
// speedup vs baseline: 2.6376x; 1.1194x over previous
#include <cuda_runtime.h>
#include <cuda_fp16.h>
#include <math_constants.h>
#include <cstdint>
#include <cstddef>

#define N_USERS 10000
#define N_NEWS  10000
#define N_ENT   100000
#define N_RELS  32
#define DIM     64
#define KNB     20
#define NNZ_CNT 500000

// -------------------- attention (mma.sync fp16) config ---------------------
#define QTILE   128
#define KTILE   64
#define QTILES  79                  // ceil(10000/128)
#define NKT     157                 // ceil(10000/64)
#define KSPL    15
#define ATT_UNITS (QTILES * KSPL)   // 1185 = 4.00 waves at 2 CTA/SM

__device__ float g_po[(size_t)ATT_UNITS * 128 * 64];
__device__ float g_pl[(size_t)ATT_UNITS * 128];
__device__ float g_pm[(size_t)ATT_UNITS * 128];

// pre-split KV in fp16 hi/lo, padded to NKT*KTILE rows (tail rows zeroed)
__device__ __half g_kvhi[(size_t)NKT * KTILE * DIM];
__device__ __half g_kvlo[(size_t)NKT * KTILE * DIM];

// smem map (bytes): Q hi/lo 16KB each; two K buffers of (hi 8KB + lo 8KB)
#define SQHI  0
#define SQLO  16384
#define SK0HI 32768
#define SK0LO 40960
#define SK1HI 49152
#define SK1LO 57344
#define SMEM_ATT 65536

// ----------------------------- helpers -------------------------------------
__device__ __forceinline__ uint32_t smem_u32(const void* p) {
    uint32_t a;
    asm("{ .reg .u64 t; cvta.to.shared.u64 t, %1; cvt.u32.u64 %0, t; }"
        : "=r"(a) : "l"(p));
    return a;
}
__device__ __forceinline__ void ldsm4(uint32_t r[4], uint32_t addr) {
    asm volatile("ldmatrix.sync.aligned.m8n8.x4.shared.b16 {%0,%1,%2,%3}, [%4];"
        : "=r"(r[0]), "=r"(r[1]), "=r"(r[2]), "=r"(r[3]) : "r"(addr));
}
__device__ __forceinline__ void ldsm4t(uint32_t r[4], uint32_t addr) {
    asm volatile("ldmatrix.sync.aligned.m8n8.x4.trans.shared.b16 {%0,%1,%2,%3}, [%4];"
        : "=r"(r[0]), "=r"(r[1]), "=r"(r[2]), "=r"(r[3]) : "r"(addr));
}
__device__ __forceinline__ void mma16816(float d[4], const uint32_t a[4],
                                         uint32_t b0, uint32_t b1) {
    asm volatile(
        "mma.sync.aligned.m16n8k16.row.col.f32.f16.f16.f32 "
        "{%0,%1,%2,%3}, {%4,%5,%6,%7}, {%8,%9}, {%0,%1,%2,%3};"
        : "+f"(d[0]), "+f"(d[1]), "+f"(d[2]), "+f"(d[3])
        : "r"(a[0]), "r"(a[1]), "r"(a[2]), "r"(a[3]), "r"(b0), "r"(b1));
}
__device__ __forceinline__ uint32_t f2h2(float x, float y) {
    __half2 h = __floats2half2_rn(x, y);
    return *reinterpret_cast<uint32_t*>(&h);
}
__device__ __forceinline__ float2 h22f2(uint32_t u) {
    __half2 h = *reinterpret_cast<__half2*>(&u);
    return __half22float2(h);
}
__device__ __forceinline__ void split_chunk(float4 a, float4 b,
                                            uint4& hi, uint4& lo) {
    hi = make_uint4(f2h2(a.x, a.y), f2h2(a.z, a.w), f2h2(b.x, b.y), f2h2(b.z, b.w));
    float2 r0 = h22f2(hi.x), r1 = h22f2(hi.y), r2 = h22f2(hi.z), r3 = h22f2(hi.w);
    lo = make_uint4(f2h2(a.x - r0.x, a.y - r0.y), f2h2(a.z - r1.x, a.w - r1.y),
                    f2h2(b.x - r2.x, b.y - r2.y), f2h2(b.z - r3.x, b.w - r3.y));
}
__device__ __forceinline__ uint32_t swadr(uint32_t base, uint32_t row, uint32_t chunk) {
    return base + row * 128u + ((chunk ^ (row & 7u)) << 4);
}
__device__ __forceinline__ void cp16(uint32_t dst, const void* src) {
    asm volatile("cp.async.ca.shared.global [%0], [%1], 16;"
                 :: "r"(dst), "l"(src) : "memory");
}
#define CP_COMMIT() asm volatile("cp.async.commit_group;" ::: "memory")
#define CP_WAIT(n)  asm volatile("cp.async.wait_group %0;" :: "n"(n) : "memory")

// ---------------------------------------------------------------------------
// Pre-split KV (news_agg) into fp16 hi/lo, zero-padding rows >= N_NEWS.
// ---------------------------------------------------------------------------
__global__ void __launch_bounds__(256) conv_kv_kernel(const float* __restrict__ kv)
{
    size_t i = (size_t)blockIdx.x * blockDim.x + threadIdx.x;
    if (i >= (size_t)NKT * KTILE * DIM) return;
    size_t row = i / DIM;
    float x = (row < N_NEWS) ? kv[i] : 0.f;
    __half h = __float2half_rn(x);
    g_kvhi[i] = h;
    g_kvlo[i] = __float2half_rn(x - __half2float(h));
}

// ---------------------------------------------------------------------------
// FA2 on mma.sync fp16: 256 thr, 8 warps x 16 q-rows. K/V tiles cp.async
// double-buffered from pre-split fp16. S = 3-term split; O = 2-term.
// ---------------------------------------------------------------------------
__global__ void __launch_bounds__(256, 2)
attn_mma_kernel(const float* __restrict__ Q)
{
    extern __shared__ char smraw[];
    const uint32_t sb = smem_u32(smraw);
    const int tid  = threadIdx.x;
    const int wrp  = tid >> 5;
    const int lane = tid & 31;
    const int qt   = blockIdx.x / KSPL;
    const int ks   = blockIdx.x % KSPL;
    const int nt   = (NKT - ks + KSPL - 1) / KSPL;

    // ---- stage Q (2 threads per row), hi/lo fp16, swizzled ----
    {
        int r = tid >> 1, hc = tid & 1;
        int gr = qt * QTILE + r;
        const float4* src = (const float4*)(Q + (size_t)gr * DIM) + hc * 8;
        #pragma unroll
        for (int i = 0; i < 4; i++) {
            float4 a, b;
            if (gr < N_USERS) { a = src[2 * i]; b = src[2 * i + 1]; }
            else { a = make_float4(0.f, 0.f, 0.f, 0.f); b = a; }
            uint4 hi, lo;
            split_chunk(a, b, hi, lo);
            uint32_t c = hc * 4 + i;
            *(uint4*)(smraw + SQHI + swadr(0, r, c)) = hi;
            *(uint4*)(smraw + SQLO + swadr(0, r, c)) = lo;
        }
    }

    // ---- cp.async tile 0 into buffer 0 (4 threads per key row) ----
    {
        int r = tid >> 2, qc = tid & 3;
        size_t key = (size_t)ks * KTILE + r;
        const char* ghi = (const char*)g_kvhi + key * 128;
        const char* glo = (const char*)g_kvlo + key * 128;
        #pragma unroll
        for (int i = 0; i < 2; i++) {
            uint32_t c = qc * 2 + i;
            cp16(sb + SK0HI + swadr(0, r, c), ghi + c * 16);
            cp16(sb + SK0LO + swadr(0, r, c), glo + c * 16);
        }
    }
    CP_COMMIT();
    __syncthreads();     // Q stores visible

    // ---- Q fragments: qh/ql[kp][4] ----
    uint32_t qh[4][4], ql[4][4];
    #pragma unroll
    for (int kp = 0; kp < 4; kp++) {
        uint32_t row = 16 * wrp + ((lane >> 3) & 1) * 8 + (lane & 7);
        uint32_t ch  = 2 * kp + ((lane >> 4) & 1);
        ldsm4(qh[kp], swadr(sb + SQHI, row, ch));
        ldsm4(ql[kp], swadr(sb + SQLO, row, ch));
    }

    float o[8][4];
    float m[2], l[2];
    #pragma unroll
    for (int n = 0; n < 8; n++)
        #pragma unroll
        for (int k = 0; k < 4; k++) o[n][k] = 0.f;
    m[0] = m[1] = -CUDART_INF_F;
    l[0] = l[1] = 0.f;

    for (int t = 0; t < nt; t++) {
        const int cur = t & 1;
        const int kbase = (ks + KSPL * t) * KTILE;

        // issue cp.async for tile t+1 into the other buffer
        if (t + 1 < nt) {
            int r = tid >> 2, qc = tid & 3;
            size_t key = (size_t)(ks + KSPL * (t + 1)) * KTILE + r;
            const char* ghi = (const char*)g_kvhi + key * 128;
            const char* glo = (const char*)g_kvlo + key * 128;
            uint32_t bh = cur ? SK0HI : SK1HI;
            uint32_t bl = cur ? SK0LO : SK1LO;
            #pragma unroll
            for (int i = 0; i < 2; i++) {
                uint32_t c = qc * 2 + i;
                cp16(sb + bh + swadr(0, r, c), ghi + c * 16);
                cp16(sb + bl + swadr(0, r, c), glo + c * 16);
            }
        }
        CP_COMMIT();
        CP_WAIT(1);      // tile t complete (newest group = t+1 may be pending)
        __syncthreads();

        const uint32_t khi = sb + (cur ? SK1HI : SK0HI);
        const uint32_t klo = sb + (cur ? SK1LO : SK0LO);

        // ---- S = Q @ K^T (3-term split) ----
        float s[8][4];
        #pragma unroll
        for (int n = 0; n < 8; n++)
            #pragma unroll
            for (int k = 0; k < 4; k++) s[n][k] = 0.f;

        #pragma unroll
        for (int kp = 0; kp < 4; kp++) {
            #pragma unroll
            for (int p = 0; p < 4; p++) {
                uint32_t key = 16u * p + ((lane >> 4) & 1) * 8 + (lane & 7);
                uint32_t ch  = 2u * kp + ((lane >> 3) & 1);
                uint32_t bh[4], bl[4];
                ldsm4(bh, swadr(khi, key, ch));
                ldsm4(bl, swadr(klo, key, ch));
                mma16816(s[2*p],   qh[kp], bh[0], bh[1]);
                mma16816(s[2*p],   ql[kp], bh[0], bh[1]);
                mma16816(s[2*p],   qh[kp], bl[0], bl[1]);
                mma16816(s[2*p+1], qh[kp], bh[2], bh[3]);
                mma16816(s[2*p+1], ql[kp], bh[2], bh[3]);
                mma16816(s[2*p+1], qh[kp], bl[2], bl[3]);
            }
        }

        // ---- mask tail keys ----
        if (kbase + KTILE > N_NEWS) {
            #pragma unroll
            for (int n = 0; n < 8; n++) {
                int c0 = kbase + 8 * n + (lane & 3) * 2;
                #pragma unroll
                for (int d = 0; d < 2; d++) {
                    if (c0 + d >= N_NEWS) {
                        s[n][d]     = -CUDART_INF_F;
                        s[n][d + 2] = -CUDART_INF_F;
                    }
                }
            }
        }

        // ---- online softmax (h = row half; 4 lanes per row) ----
        #pragma unroll
        for (int h = 0; h < 2; h++) {
            float mx = -CUDART_INF_F;
            #pragma unroll
            for (int n = 0; n < 8; n++)
                mx = fmaxf(mx, fmaxf(s[n][2*h], s[n][2*h+1]));
            mx = fmaxf(mx, __shfl_xor_sync(0xffffffffu, mx, 1));
            mx = fmaxf(mx, __shfl_xor_sync(0xffffffffu, mx, 2));
            float mn = fmaxf(m[h], mx);
            float sc = __expf(m[h] - mn);
            m[h] = mn;
            l[h] *= sc;
            #pragma unroll
            for (int n = 0; n < 8; n++) {
                o[n][2*h]   *= sc;
                o[n][2*h+1] *= sc;
                float e0 = __expf(s[n][2*h]   - mn);
                float e1 = __expf(s[n][2*h+1] - mn);
                uint32_t u = f2h2(e0, e1);   // round like the MMA will see
                float2 er = h22f2(u);
                s[n][2*h]   = er.x;
                s[n][2*h+1] = er.y;
                l[h] += er.x + er.y;
            }
        }

        // ---- O += P @ V (trans ldmatrix on same K buffers; hi+lo) ----
        #pragma unroll
        for (int kk = 0; kk < 4; kk++) {
            uint32_t pa[4];
            pa[0] = f2h2(s[2*kk][0],   s[2*kk][1]);
            pa[1] = f2h2(s[2*kk][2],   s[2*kk][3]);
            pa[2] = f2h2(s[2*kk+1][0], s[2*kk+1][1]);
            pa[3] = f2h2(s[2*kk+1][2], s[2*kk+1][3]);
            #pragma unroll
            for (int p = 0; p < 4; p++) {
                uint32_t key = 16u * kk + ((lane >> 3) & 1) * 8 + (lane & 7);
                uint32_t ch  = 2u * p + ((lane >> 4) & 1);
                uint32_t vh[4], vl[4];
                ldsm4t(vh, swadr(khi, key, ch));
                ldsm4t(vl, swadr(klo, key, ch));
                mma16816(o[2*p],   pa, vh[0], vh[1]);
                mma16816(o[2*p],   pa, vl[0], vl[1]);
                mma16816(o[2*p+1], pa, vh[2], vh[3]);
                mma16816(o[2*p+1], pa, vl[2], vl[3]);
            }
        }
        __syncthreads();   // reads of buf[cur] done before it is refilled
    }

    // ---- reduce l across the 4 lanes of each row ----
    #pragma unroll
    for (int h = 0; h < 2; h++) {
        l[h] += __shfl_xor_sync(0xffffffffu, l[h], 1);
        l[h] += __shfl_xor_sync(0xffffffffu, l[h], 2);
    }

    // ---- write partial (unnormalized O, m, l) ----
    const int g = lane >> 2;
    #pragma unroll
    for (int h = 0; h < 2; h++) {
        int row = 16 * wrp + 8 * h + g;
        float* pb = g_po + ((size_t)blockIdx.x * 128 + row) * 64;
        #pragma unroll
        for (int n = 0; n < 8; n++) {
            int c = 8 * n + (lane & 3) * 2;
            *(float2*)(pb + c) = make_float2(o[n][2*h], o[n][2*h+1]);
        }
        if ((lane & 3) == 0) {
            g_pm[(size_t)blockIdx.x * 128 + row] = m[h];
            g_pl[(size_t)blockIdx.x * 128 + row] = l[h];
        }
    }
}

// ---------------------------------------------------------------------------
// Aggregation kernel: one warp per row; relation table cached in smem (8KB).
// ---------------------------------------------------------------------------
__global__ void __launch_bounds__(256) agg_kernel(
    const float* __restrict__ head,
    const float* __restrict__ ent,
    const float* __restrict__ rel,
    const int*   __restrict__ nbe,
    const int*   __restrict__ nbr,
    float* __restrict__ out, int N)
{
    __shared__ float relS[N_RELS * DIM];
    for (int i = threadIdx.x; i < N_RELS * DIM; i += blockDim.x)
        relS[i] = rel[i];
    __syncthreads();

    int w    = (blockIdx.x * blockDim.x + threadIdx.x) >> 5;
    int lane = threadIdx.x & 31;
    if (w >= N) return;

    const float2 h = ((const float2*)(head + (size_t)w * DIM))[lane];
    const int base = w * KNB;

    int ridx[KNB], eidx[KNB];
    #pragma unroll
    for (int k = 0; k < KNB; k++) {
        ridx[k] = __ldg(nbr + base + k);
        eidx[k] = __ldg(nbe + base + k);
    }

    float sx = 0.f, sy = 0.f;
    #pragma unroll
    for (int k = 0; k < KNB; k++) {
        float2 rr = ((const float2*)(relS + ridx[k] * DIM))[lane];
        sx += rr.x * rr.x;
        sy += rr.y * rr.y;
    }
    float hnx = fabsf(h.x) * sqrtf(sx);
    float hny = fabsf(h.y) * sqrtf(sy);

    float m = 0.f, l = 0.f, ax = 0.f, ay = 0.f;
    #pragma unroll
    for (int k = 0; k < KNB; k++) {
        float2 rr = ((const float2*)(relS + ridx[k] * DIM))[lane];
        float2 tt = ((const float2*)(ent + (size_t)eidx[k] * DIM))[lane];
        float p = tt.x * rr.x * hnx + tt.y * rr.y * hny;
        #pragma unroll
        for (int off = 16; off; off >>= 1)
            p += __shfl_xor_sync(0xffffffffu, p, off);
        float a2 = p * p;
        if (k == 0) {
            m = a2; l = 1.f; ax = tt.x; ay = tt.y;
        } else {
            float mn = fmaxf(m, a2);
            float sc = __expf(m - mn);
            float e  = __expf(a2 - mn);
            l  = l  * sc + e;
            ax = ax * sc + e * tt.x;
            ay = ay * sc + e * tt.y;
            m = mn;
        }
    }
    float inv = 1.f / l;
    ((float2*)(out + (size_t)w * DIM))[lane] = make_float2(ax * inv, ay * inv);
}

// ---------------------------------------------------------------------------
__global__ void __launch_bounds__(256) segsum_kernel(
    const int*   __restrict__ rows,
    const int*   __restrict__ cols,
    const float* __restrict__ vals,
    const float* __restrict__ news_agg,
    float* __restrict__ user_seg, int nnz)
{
    int w    = (blockIdx.x * blockDim.x + threadIdx.x) >> 5;
    int lane = threadIdx.x & 31;
    if (w >= nnz) return;
    int r   = __ldg(rows + w);
    int c   = __ldg(cols + w);
    float v = __ldg(vals + w);
    float2 g = ((const float2*)(news_agg + (size_t)c * DIM))[lane];
    atomicAdd(user_seg + (size_t)r * DIM + 2 * lane,     v * g.x);
    atomicAdd(user_seg + (size_t)r * DIM + 2 * lane + 1, v * g.y);
}

// ---------------------------------------------------------------------------
// Combine split partials: M = max m_s; attn = (sum e_s O_s)/(sum e_s l_s);
// user = seg*(1+attn).
// ---------------------------------------------------------------------------
__global__ void __launch_bounds__(256) combine_kernel(float* __restrict__ user_out)
{
    int w    = (blockIdx.x * blockDim.x + threadIdx.x) >> 5;
    int lane = threadIdx.x & 31;
    if (w >= N_USERS) return;
    int qt = w >> 7, r = w & 127;

    float M = -CUDART_INF_F;
    float ms[KSPL], ls[KSPL];
    #pragma unroll
    for (int s = 0; s < KSPL; s++) {
        size_t u = (size_t)(qt * KSPL + s);
        ms[s] = g_pm[u * 128 + r];
        ls[s] = g_pl[u * 128 + r];
        M = fmaxf(M, ms[s]);
    }
    float L = 0.f, ax = 0.f, ay = 0.f;
    #pragma unroll
    for (int s = 0; s < KSPL; s++) {
        size_t u = (size_t)(qt * KSPL + s);
        float e = __expf(ms[s] - M);
        L += e * ls[s];
        float2 o2 = ((const float2*)(g_po + (u * 128 + r) * 64))[lane];
        ax += e * o2.x;
        ay += e * o2.y;
    }
    float inv = 1.f / L;
    float2* up = (float2*)(user_out + (size_t)w * DIM);
    float2 sg = up[lane];
    up[lane] = make_float2(sg.x + ax * inv * sg.x,
                           sg.y + ay * inv * sg.y);
}

// ---------------------------------------------------------------------------
extern "C" void kernel_launch(void* const* d_in, const int* in_sizes, int n_in,
                              void* d_out, int out_size)
{
    const float* user_emb = (const float*)d_in[0];
    const float* news_emb = (const float*)d_in[1];
    const float* ent_emb  = (const float*)d_in[2];
    const float* rel_emb  = (const float*)d_in[3];
    const int*   news_ent = (const int*)d_in[4];
    const int*   news_rel = (const int*)d_in[5];
    const int*   nb_ent   = (const int*)d_in[6];
    const int*   nb_rel   = (const int*)d_in[7];
    const int*   irows    = (const int*)d_in[8];
    const int*   icols    = (const int*)d_in[9];
    const float* ivals    = (const float*)d_in[10];

    float* out      = (float*)d_out;
    float* news_out = out;
    float* ent_out  = out + (size_t)N_NEWS * DIM;
    float* user_out = ent_out + (size_t)N_ENT * DIM;

    agg_kernel<<<(N_NEWS + 7) / 8, 256>>>(news_emb, ent_emb, rel_emb,
                                          news_ent, news_rel, news_out, N_NEWS);
    agg_kernel<<<(N_ENT + 7) / 8, 256>>>(ent_emb, ent_emb, rel_emb,
                                         nb_ent, nb_rel, ent_out, N_ENT);
    cudaMemsetAsync(user_out, 0, (size_t)N_USERS * DIM * sizeof(float));
    segsum_kernel<<<(NNZ_CNT + 7) / 8, 256>>>(irows, icols, ivals,
                                              news_out, user_out, NNZ_CNT);
    // pre-split KV to fp16 hi/lo
    {
        size_t tot = (size_t)NKT * KTILE * DIM;
        conv_kv_kernel<<<(unsigned)((tot + 255) / 256), 256>>>(news_out);
    }
    cudaFuncSetAttribute(attn_mma_kernel,
                         cudaFuncAttributeMaxDynamicSharedMemorySize, SMEM_ATT);
    attn_mma_kernel<<<ATT_UNITS, 256, SMEM_ATT>>>(user_emb);
    combine_kernel<<<(N_USERS + 7) / 8, 256>>>(user_out);
}